// round 2
// baseline (speedup 1.0000x reference)
#include <cuda_runtime.h>
#include <stdint.h>
#include <stddef.h>

// Problem constants
#define B_ 4
#define S_ 2048
#define HID_ 768
#define H_ 12
#define D_ 64
static const int   M_ROWS    = B_ * S_;          // 8192
static const int   BH_       = B_ * H_;          // 48
static const int   OUT_ELEMS = M_ROWS * HID_;    // 6,291,456
#define SCALE_ 0.125f

// Scratch: q, k, v (BHSD each) + context (row-major [8192,768])
__device__ float g_scratch[4ull * 6291456ull];

// ---------------------------------------------------------------------------
// GEMM: C[8192,768] = X[8192,768] @ W[768,768] + bias
// MODE 0: scatter output to BHSD layout (for q/k/v); MODE 1: row-major.
// Block tile 128x128, BK=16, 256 threads, 8x8 per-thread tile.
// ---------------------------------------------------------------------------
template <int MODE>
__global__ __launch_bounds__(256) void gemm_bias(
    const float* __restrict__ X, const float* __restrict__ W,
    const float* __restrict__ bias, float* __restrict__ out)
{
    __shared__ float Xs[16][132];   // [k][m]
    __shared__ float Ws[16][132];   // [k][n]
    const int tid = threadIdx.x;
    const int ty  = tid >> 4;       // 0..15 -> m
    const int tx  = tid & 15;       // 0..15 -> n
    const int m0  = blockIdx.y * 128;
    const int n0  = blockIdx.x * 128;

    float acc[8][8];
#pragma unroll
    for (int i = 0; i < 8; i++)
#pragma unroll
        for (int j = 0; j < 8; j++) acc[i][j] = 0.f;

    for (int k0 = 0; k0 < HID_; k0 += 16) {
        // X tile 128x16 -> Xs[k][m] (transpose-in-smem)
#pragma unroll
        for (int ii = 0; ii < 2; ii++) {
            int f  = tid * 2 + ii;          // 0..511
            int m  = f >> 2;                // 0..127
            int kq = f & 3;                 // 0..3
            float4 v = *(const float4*)(X + (size_t)(m0 + m) * HID_ + k0 + kq * 4);
            Xs[kq * 4 + 0][m] = v.x;
            Xs[kq * 4 + 1][m] = v.y;
            Xs[kq * 4 + 2][m] = v.z;
            Xs[kq * 4 + 3][m] = v.w;
        }
        // W tile 16x128 -> Ws[k][n]
#pragma unroll
        for (int ii = 0; ii < 2; ii++) {
            int f  = tid * 2 + ii;          // 0..511
            int kr = f >> 5;                // 0..15
            int nq = f & 31;                // 0..31
            float4 v = *(const float4*)(W + (size_t)(k0 + kr) * HID_ + n0 + nq * 4);
            *(float4*)&Ws[kr][nq * 4] = v;
        }
        __syncthreads();
#pragma unroll
        for (int k = 0; k < 16; k++) {
            float a[8], b[8];
            *(float4*)&a[0] = *(const float4*)&Xs[k][ty * 8];
            *(float4*)&a[4] = *(const float4*)&Xs[k][ty * 8 + 4];
            *(float4*)&b[0] = *(const float4*)&Ws[k][tx * 8];
            *(float4*)&b[4] = *(const float4*)&Ws[k][tx * 8 + 4];
#pragma unroll
            for (int i = 0; i < 8; i++)
#pragma unroll
                for (int j = 0; j < 8; j++) acc[i][j] += a[i] * b[j];
        }
        __syncthreads();
    }

#pragma unroll
    for (int i = 0; i < 8; i++) {
        int m = m0 + ty * 8 + i;
#pragma unroll
        for (int j = 0; j < 8; j++) {
            int n = n0 + tx * 8 + j;
            float v = acc[i][j] + bias[n];
            if (MODE == 0) {
                int bb = m >> 11;      // / 2048
                int s  = m & 2047;
                int h  = n >> 6;       // / 64
                int d  = n & 63;
                out[(((size_t)(bb * H_ + h) * S_ + s) << 6) + d] = v;
            } else {
                out[(size_t)m * HID_ + n] = v;
            }
        }
    }
}

// ---------------------------------------------------------------------------
// Scores: raw masked scaled scores -> prob buffer.
// C[q,k] = SCALE * sum_d q[q,d]*k[k,d]; masked -> -1e9.
// mask is int32 (bool marshalled as int32): nonzero -> masked.
// Block tile 128x128 over (q,k); K-dim = 64 in 4 chunks of 16.
// ---------------------------------------------------------------------------
__global__ __launch_bounds__(256) void scores_kernel(
    const float* __restrict__ qg, const float* __restrict__ kg,
    const int* __restrict__ mask, float* __restrict__ probs)
{
    __shared__ float Qs[16][132];   // [d][qrow]
    __shared__ float Ks[16][132];   // [d][krow]
    const int tid = threadIdx.x;
    const int ty  = tid >> 4;
    const int tx  = tid & 15;
    const int bh  = blockIdx.z;
    const int q0  = blockIdx.y * 128;
    const int k0  = blockIdx.x * 128;
    const int bb  = bh / H_;
    const float* qbase = qg + (size_t)bh * S_ * D_;
    const float* kbase = kg + (size_t)bh * S_ * D_;

    float acc[8][8];
#pragma unroll
    for (int i = 0; i < 8; i++)
#pragma unroll
        for (int j = 0; j < 8; j++) acc[i][j] = 0.f;

    for (int d0 = 0; d0 < D_; d0 += 16) {
#pragma unroll
        for (int ii = 0; ii < 2; ii++) {
            int f  = tid * 2 + ii;
            int m  = f >> 2;
            int dq = f & 3;
            float4 v = *(const float4*)(qbase + (size_t)(q0 + m) * D_ + d0 + dq * 4);
            Qs[dq * 4 + 0][m] = v.x; Qs[dq * 4 + 1][m] = v.y;
            Qs[dq * 4 + 2][m] = v.z; Qs[dq * 4 + 3][m] = v.w;
        }
#pragma unroll
        for (int ii = 0; ii < 2; ii++) {
            int f  = tid * 2 + ii;
            int m  = f >> 2;
            int dq = f & 3;
            float4 v = *(const float4*)(kbase + (size_t)(k0 + m) * D_ + d0 + dq * 4);
            Ks[dq * 4 + 0][m] = v.x; Ks[dq * 4 + 1][m] = v.y;
            Ks[dq * 4 + 2][m] = v.z; Ks[dq * 4 + 3][m] = v.w;
        }
        __syncthreads();
#pragma unroll
        for (int k = 0; k < 16; k++) {
            float a[8], b[8];
            *(float4*)&a[0] = *(const float4*)&Qs[k][ty * 8];
            *(float4*)&a[4] = *(const float4*)&Qs[k][ty * 8 + 4];
            *(float4*)&b[0] = *(const float4*)&Ks[k][tx * 8];
            *(float4*)&b[4] = *(const float4*)&Ks[k][tx * 8 + 4];
#pragma unroll
            for (int i = 0; i < 8; i++)
#pragma unroll
                for (int j = 0; j < 8; j++) acc[i][j] += a[i] * b[j];
        }
        __syncthreads();
    }

    const int* mrow = mask + (size_t)bb * S_ * S_;
#pragma unroll
    for (int i = 0; i < 8; i++) {
        int qrow = q0 + ty * 8 + i;
        const int* mp = mrow + (size_t)qrow * S_ + k0 + tx * 8;
        int4 m0v = *(const int4*)(mp);
        int4 m1v = *(const int4*)(mp + 4);
        int mm[8] = {m0v.x, m0v.y, m0v.z, m0v.w, m1v.x, m1v.y, m1v.z, m1v.w};
        float vals[8];
#pragma unroll
        for (int j = 0; j < 8; j++) {
            float v = acc[i][j] * SCALE_;
            if (mm[j] != 0) v = -1e9f;
            vals[j] = v;
        }
        float* dst = probs + ((size_t)bh * S_ + qrow) * S_ + k0 + tx * 8;
        *(float4*)dst       = *(float4*)&vals[0];
        *(float4*)(dst + 4) = *(float4*)&vals[4];
    }
}

// ---------------------------------------------------------------------------
// Row softmax in-place over prob buffer: one block per row of 2048.
// ---------------------------------------------------------------------------
__global__ __launch_bounds__(256) void softmax_kernel(float* __restrict__ probs)
{
    __shared__ float smax[8];
    __shared__ float ssum[8];
    __shared__ float sbc[2];
    const size_t row = blockIdx.x;
    float* p = probs + row * (size_t)S_;
    const int tid  = threadIdx.x;
    const int wid  = tid >> 5;
    const int lane = tid & 31;

    float4 v0 = *(float4*)(p + tid * 8);
    float4 v1 = *(float4*)(p + tid * 8 + 4);

    float mx = fmaxf(fmaxf(fmaxf(v0.x, v0.y), fmaxf(v0.z, v0.w)),
                     fmaxf(fmaxf(v1.x, v1.y), fmaxf(v1.z, v1.w)));
#pragma unroll
    for (int o = 16; o; o >>= 1) mx = fmaxf(mx, __shfl_xor_sync(0xffffffffu, mx, o));
    if (lane == 0) smax[wid] = mx;
    __syncthreads();
    if (tid == 0) {
        float m = smax[0];
#pragma unroll
        for (int i = 1; i < 8; i++) m = fmaxf(m, smax[i]);
        sbc[0] = m;
    }
    __syncthreads();
    mx = sbc[0];

    float e[8];
    e[0] = __expf(v0.x - mx); e[1] = __expf(v0.y - mx);
    e[2] = __expf(v0.z - mx); e[3] = __expf(v0.w - mx);
    e[4] = __expf(v1.x - mx); e[5] = __expf(v1.y - mx);
    e[6] = __expf(v1.z - mx); e[7] = __expf(v1.w - mx);
    float s = 0.f;
#pragma unroll
    for (int i = 0; i < 8; i++) s += e[i];
#pragma unroll
    for (int o = 16; o; o >>= 1) s += __shfl_xor_sync(0xffffffffu, s, o);
    if (lane == 0) ssum[wid] = s;
    __syncthreads();
    if (tid == 0) {
        float t = 0.f;
#pragma unroll
        for (int i = 0; i < 8; i++) t += ssum[i];
        sbc[1] = 1.f / t;
    }
    __syncthreads();
    float inv = sbc[1];

    float4 o0 = make_float4(e[0] * inv, e[1] * inv, e[2] * inv, e[3] * inv);
    float4 o1 = make_float4(e[4] * inv, e[5] * inv, e[6] * inv, e[7] * inv);
    *(float4*)(p + tid * 8)     = o0;
    *(float4*)(p + tid * 8 + 4) = o1;
}

// ---------------------------------------------------------------------------
// PV: context[q, h*64+d] += sum_k P[bh,q,k] * v[bh,k,d]
// Block tile 256(q) x 64(d), BK=32, 256 threads, 8x8 per-thread tile.
// ---------------------------------------------------------------------------
__global__ __launch_bounds__(256) void pv_kernel(
    const float* __restrict__ probs, const float* __restrict__ vg,
    float* __restrict__ ctx)
{
    __shared__ float Pst[32][260];  // [k][qrow]
    __shared__ float Vs[32][68];    // [k][d]
    const int tid = threadIdx.x;
    const int ty  = tid >> 3;       // 0..31 -> q
    const int tx  = tid & 7;        // 0..7  -> d
    const int q0  = blockIdx.x * 256;
    const int bh  = blockIdx.y;
    const float* vbase = vg + (size_t)bh * S_ * D_;
    const size_t prow0 = (size_t)bh * S_ + q0;

    float acc[8][8];
#pragma unroll
    for (int i = 0; i < 8; i++)
#pragma unroll
        for (int j = 0; j < 8; j++) acc[i][j] = 0.f;

    for (int k0 = 0; k0 < S_; k0 += 32) {
        // P tile 256x32 -> Pst[k][m]
#pragma unroll
        for (int ii = 0; ii < 8; ii++) {
            int f  = tid + 256 * ii;    // 0..2047
            int m  = f >> 3;            // 0..255
            int kq = f & 7;             // 0..7
            float4 v = *(const float4*)(probs + (prow0 + m) * S_ + k0 + kq * 4);
            Pst[kq * 4 + 0][m] = v.x; Pst[kq * 4 + 1][m] = v.y;
            Pst[kq * 4 + 2][m] = v.z; Pst[kq * 4 + 3][m] = v.w;
        }
        // V tile 32x64 -> Vs[k][d]
#pragma unroll
        for (int ii = 0; ii < 2; ii++) {
            int f  = tid + 256 * ii;    // 0..511
            int k  = f >> 4;            // 0..31
            int dq = f & 15;            // 0..15
            *(float4*)&Vs[k][dq * 4] = *(const float4*)(vbase + (size_t)(k0 + k) * D_ + dq * 4);
        }
        __syncthreads();
#pragma unroll
        for (int k = 0; k < 32; k++) {
            float a[8], b[8];
            *(float4*)&a[0] = *(const float4*)&Pst[k][ty * 8];
            *(float4*)&a[4] = *(const float4*)&Pst[k][ty * 8 + 4];
            *(float4*)&b[0] = *(const float4*)&Vs[k][tx * 8];
            *(float4*)&b[4] = *(const float4*)&Vs[k][tx * 8 + 4];
#pragma unroll
            for (int i = 0; i < 8; i++)
#pragma unroll
                for (int j = 0; j < 8; j++) acc[i][j] += a[i] * b[j];
        }
        __syncthreads();
    }

    const int bb = bh / H_;
    const int h  = bh % H_;
#pragma unroll
    for (int i = 0; i < 8; i++) {
        int q = q0 + ty * 8 + i;
        float* dst = ctx + ((size_t)(bb * S_ + q)) * HID_ + h * D_ + tx * 8;
        float4 o0 = make_float4(acc[i][0], acc[i][1], acc[i][2], acc[i][3]);
        float4 o1 = make_float4(acc[i][4], acc[i][5], acc[i][6], acc[i][7]);
        *(float4*)dst       = o0;
        *(float4*)(dst + 4) = o1;
    }
}

// ---------------------------------------------------------------------------
extern "C" void kernel_launch(void* const* d_in, const int* in_sizes, int n_in,
                              void* d_out, int out_size)
{
    (void)in_sizes; (void)n_in; (void)out_size;
    const float* Q  = (const float*)d_in[0];
    const float* K  = (const float*)d_in[1];
    const float* V  = (const float*)d_in[2];
    const int*   mask = (const int*)d_in[3];
    const float* Wq = (const float*)d_in[4];
    const float* bq = (const float*)d_in[5];
    const float* Wk = (const float*)d_in[6];
    const float* bk = (const float*)d_in[7];
    const float* Wv = (const float*)d_in[8];
    const float* bv = (const float*)d_in[9];
    const float* Wo = (const float*)d_in[10];
    const float* bo = (const float*)d_in[11];

    float* out   = (float*)d_out;
    float* probs = out + OUT_ELEMS;   // attn_prob region: [48, 2048, 2048]

    float* scratch = nullptr;
    cudaGetSymbolAddress((void**)&scratch, g_scratch);
    float* gq   = scratch;
    float* gk   = scratch + (size_t)OUT_ELEMS;
    float* gv   = scratch + 2ull * OUT_ELEMS;
    float* gctx = scratch + 3ull * OUT_ELEMS;

    dim3 gproj(HID_ / 128, M_ROWS / 128);   // (6, 64)
    gemm_bias<0><<<gproj, 256>>>(Q, Wq, bq, gq);
    gemm_bias<0><<<gproj, 256>>>(K, Wk, bk, gk);
    gemm_bias<0><<<gproj, 256>>>(V, Wv, bv, gv);

    scores_kernel<<<dim3(S_ / 128, S_ / 128, BH_), 256>>>(gq, gk, mask, probs);
    softmax_kernel<<<dim3(BH_ * S_), 256>>>(probs);
    pv_kernel<<<dim3(S_ / 256, BH_), 256>>>(probs, gv, gctx);

    gemm_bias<1><<<gproj, 256>>>(gctx, Wo, bo, out);
}

// round 3
// speedup vs baseline: 2.0406x; 2.0406x over previous
#include <cuda_runtime.h>
#include <stdint.h>
#include <stddef.h>

#define B_ 4
#define S_ 2048
#define HID_ 768
#define H_ 12
#define D_ 64
#define BH_ 48
#define MROWS 8192
#define OUTE 6291456
#define SCALE_ 0.125f

// Scratch: q, k, v (BHSD each) + context (row-major [8192,768])
__device__ float g_scratch[4ull * 6291456ull];

// ---------------------------------------------------------------------------
// tf32 helpers
// ---------------------------------------------------------------------------
__device__ __forceinline__ uint32_t f2t(float f) {
    uint32_t r;
    asm("cvt.rna.tf32.f32 %0, %1;" : "=r"(r) : "f"(f));
    return r;
}

__device__ __forceinline__ void mma8(float* c,
    uint32_t a0, uint32_t a1, uint32_t a2, uint32_t a3,
    uint32_t b0, uint32_t b1)
{
    asm volatile(
        "mma.sync.aligned.m16n8k8.row.col.f32.tf32.tf32.f32 "
        "{%0,%1,%2,%3}, {%4,%5,%6,%7}, {%8,%9}, {%0,%1,%2,%3};"
        : "+f"(c[0]), "+f"(c[1]), "+f"(c[2]), "+f"(c[3])
        : "r"(a0), "r"(a1), "r"(a2), "r"(a3), "r"(b0), "r"(b1));
}

// ---------------------------------------------------------------------------
// Projection GEMM (tensor core): C[8192,768] = X @ W + bias
// Block 128x128, BK=32, 8 warps (2x4), warp tile 64x32 (4x4 frags of 16x8).
// MODE 0: scatter to BHSD; MODE 1: row-major.
// ---------------------------------------------------------------------------
template <int MODE>
__global__ __launch_bounds__(256) void gemm_bias_tc(
    const float* __restrict__ X, const float* __restrict__ W,
    const float* __restrict__ bias, float* __restrict__ out)
{
    __shared__ uint32_t Xs[128][36];   // [m][k], tf32 bits
    __shared__ uint32_t Ws[32][136];   // [k][n], tf32 bits

    const int tid  = threadIdx.x;
    const int w    = tid >> 5;
    const int lane = tid & 31;
    const int g    = lane >> 2;        // 0..7
    const int t    = lane & 3;         // 0..3
    const int wm   = (w & 1) * 64;
    const int wn   = (w >> 1) * 32;
    const int m0   = blockIdx.y * 128;
    const int n0   = blockIdx.x * 128;

    float acc[4][4][4];
#pragma unroll
    for (int mi = 0; mi < 4; mi++)
#pragma unroll
        for (int ni = 0; ni < 4; ni++)
#pragma unroll
            for (int r = 0; r < 4; r++) acc[mi][ni][r] = 0.f;

    for (int k0 = 0; k0 < HID_; k0 += 32) {
#pragma unroll
        for (int i = 0; i < 4; i++) {
            int f = tid + 256 * i;      // 0..1023
            int r = f >> 3;             // 0..127
            int q = f & 7;              // 0..7
            float4 v = *(const float4*)(X + (size_t)(m0 + r) * HID_ + k0 + q * 4);
            uint4 u = make_uint4(f2t(v.x), f2t(v.y), f2t(v.z), f2t(v.w));
            *(uint4*)&Xs[r][q * 4] = u;
        }
#pragma unroll
        for (int i = 0; i < 4; i++) {
            int f = tid + 256 * i;
            int r = f >> 5;             // 0..31
            int q = f & 31;             // 0..31
            float4 v = *(const float4*)(W + (size_t)(k0 + r) * HID_ + n0 + q * 4);
            uint4 u = make_uint4(f2t(v.x), f2t(v.y), f2t(v.z), f2t(v.w));
            *(uint4*)&Ws[r][q * 4] = u;
        }
        __syncthreads();

#pragma unroll
        for (int kk = 0; kk < 32; kk += 8) {
            uint32_t a[4][4], b[4][2];
#pragma unroll
            for (int mi = 0; mi < 4; mi++) {
                int mr = wm + 16 * mi + g;
                a[mi][0] = Xs[mr][kk + t];
                a[mi][1] = Xs[mr + 8][kk + t];
                a[mi][2] = Xs[mr][kk + t + 4];
                a[mi][3] = Xs[mr + 8][kk + t + 4];
            }
#pragma unroll
            for (int ni = 0; ni < 4; ni++) {
                b[ni][0] = Ws[kk + t][wn + 8 * ni + g];
                b[ni][1] = Ws[kk + t + 4][wn + 8 * ni + g];
            }
#pragma unroll
            for (int mi = 0; mi < 4; mi++)
#pragma unroll
                for (int ni = 0; ni < 4; ni++)
                    mma8(acc[mi][ni], a[mi][0], a[mi][1], a[mi][2], a[mi][3],
                         b[ni][0], b[ni][1]);
        }
        __syncthreads();
    }

#pragma unroll
    for (int mi = 0; mi < 4; mi++) {
        int r0 = m0 + wm + 16 * mi + g;
        int r1 = r0 + 8;
#pragma unroll
        for (int ni = 0; ni < 4; ni++) {
            int col = n0 + wn + 8 * ni + 2 * t;
            float bb0 = bias[col], bb1 = bias[col + 1];
            float2 v0 = make_float2(acc[mi][ni][0] + bb0, acc[mi][ni][1] + bb1);
            float2 v1 = make_float2(acc[mi][ni][2] + bb0, acc[mi][ni][3] + bb1);
            if (MODE == 0) {
                int h = col >> 6, d = col & 63;
                int b0r = r0 >> 11, s0 = r0 & 2047;
                int b1r = r1 >> 11, s1 = r1 & 2047;
                *(float2*)&out[(((size_t)(b0r * H_ + h) * S_ + s0) << 6) + d] = v0;
                *(float2*)&out[(((size_t)(b1r * H_ + h) * S_ + s1) << 6) + d] = v1;
            } else {
                *(float2*)&out[(size_t)r0 * HID_ + col] = v0;
                *(float2*)&out[(size_t)r1 * HID_ + col] = v1;
            }
        }
    }
}

// ---------------------------------------------------------------------------
// Scores (tensor core): raw masked scaled scores -> prob buffer.
// Block 128x128 over (q,k); full D=64 tiles in smem (dynamic, ~68KB).
// ---------------------------------------------------------------------------
__global__ __launch_bounds__(256) void scores_tc(
    const float* __restrict__ qg, const float* __restrict__ kg,
    const int* __restrict__ mask, float* __restrict__ probs)
{
    extern __shared__ uint32_t sh[];
    uint32_t (*Qs)[68] = (uint32_t(*)[68])sh;            // [q][d]
    uint32_t (*Ks)[68] = (uint32_t(*)[68])(sh + 128 * 68); // [kk][d]

    const int tid  = threadIdx.x;
    const int w    = tid >> 5;
    const int lane = tid & 31;
    const int g    = lane >> 2;
    const int t    = lane & 3;
    const int wm   = (w & 1) * 64;
    const int wn   = (w >> 1) * 32;
    const int bh   = blockIdx.z;
    const int q0   = blockIdx.y * 128;
    const int k0   = blockIdx.x * 128;
    const int bb   = bh / H_;
    const float* qbase = qg + (size_t)bh * S_ * D_;
    const float* kbase = kg + (size_t)bh * S_ * D_;

#pragma unroll
    for (int i = 0; i < 8; i++) {
        int f = tid + 256 * i;          // 0..2047
        int r = f >> 4;                 // 0..127
        int q = f & 15;                 // 0..15
        float4 v = *(const float4*)(qbase + (size_t)(q0 + r) * D_ + q * 4);
        uint4 u = make_uint4(f2t(v.x), f2t(v.y), f2t(v.z), f2t(v.w));
        *(uint4*)&Qs[r][q * 4] = u;
    }
#pragma unroll
    for (int i = 0; i < 8; i++) {
        int f = tid + 256 * i;
        int r = f >> 4;
        int q = f & 15;
        float4 v = *(const float4*)(kbase + (size_t)(k0 + r) * D_ + q * 4);
        uint4 u = make_uint4(f2t(v.x), f2t(v.y), f2t(v.z), f2t(v.w));
        *(uint4*)&Ks[r][q * 4] = u;
    }
    __syncthreads();

    float acc[4][4][4];
#pragma unroll
    for (int mi = 0; mi < 4; mi++)
#pragma unroll
        for (int ni = 0; ni < 4; ni++)
#pragma unroll
            for (int r = 0; r < 4; r++) acc[mi][ni][r] = 0.f;

#pragma unroll
    for (int kk = 0; kk < 64; kk += 8) {
        uint32_t a[4][4], b[4][2];
#pragma unroll
        for (int mi = 0; mi < 4; mi++) {
            int mr = wm + 16 * mi + g;
            a[mi][0] = Qs[mr][kk + t];
            a[mi][1] = Qs[mr + 8][kk + t];
            a[mi][2] = Qs[mr][kk + t + 4];
            a[mi][3] = Qs[mr + 8][kk + t + 4];
        }
#pragma unroll
        for (int ni = 0; ni < 4; ni++) {
            int nr = wn + 8 * ni + g;
            b[ni][0] = Ks[nr][kk + t];
            b[ni][1] = Ks[nr][kk + t + 4];
        }
#pragma unroll
        for (int mi = 0; mi < 4; mi++)
#pragma unroll
            for (int ni = 0; ni < 4; ni++)
                mma8(acc[mi][ni], a[mi][0], a[mi][1], a[mi][2], a[mi][3],
                     b[ni][0], b[ni][1]);
    }

    const int* mrow = mask + (size_t)bb * S_ * S_;
#pragma unroll
    for (int mi = 0; mi < 4; mi++) {
        int r0 = q0 + wm + 16 * mi + g;
        int r1 = r0 + 8;
#pragma unroll
        for (int ni = 0; ni < 4; ni++) {
            int col = k0 + wn + 8 * ni + 2 * t;
            int2 mq0 = *(const int2*)(mrow + (size_t)r0 * S_ + col);
            int2 mq1 = *(const int2*)(mrow + (size_t)r1 * S_ + col);
            float2 v0, v1;
            v0.x = mq0.x ? -1e9f : acc[mi][ni][0] * SCALE_;
            v0.y = mq0.y ? -1e9f : acc[mi][ni][1] * SCALE_;
            v1.x = mq1.x ? -1e9f : acc[mi][ni][2] * SCALE_;
            v1.y = mq1.y ? -1e9f : acc[mi][ni][3] * SCALE_;
            *(float2*)&probs[((size_t)bh * S_ + r0) * S_ + col] = v0;
            *(float2*)&probs[((size_t)bh * S_ + r1) * S_ + col] = v1;
        }
    }
}

// ---------------------------------------------------------------------------
// Row softmax in-place: one block per row of 2048.
// ---------------------------------------------------------------------------
__global__ __launch_bounds__(256) void softmax_kernel(float* __restrict__ probs)
{
    __shared__ float smax[8];
    __shared__ float ssum[8];
    __shared__ float sbc[2];
    const size_t row = blockIdx.x;
    float* p = probs + row * (size_t)S_;
    const int tid  = threadIdx.x;
    const int wid  = tid >> 5;
    const int lane = tid & 31;

    float4 v0 = *(float4*)(p + tid * 8);
    float4 v1 = *(float4*)(p + tid * 8 + 4);

    float mx = fmaxf(fmaxf(fmaxf(v0.x, v0.y), fmaxf(v0.z, v0.w)),
                     fmaxf(fmaxf(v1.x, v1.y), fmaxf(v1.z, v1.w)));
#pragma unroll
    for (int o = 16; o; o >>= 1) mx = fmaxf(mx, __shfl_xor_sync(0xffffffffu, mx, o));
    if (lane == 0) smax[wid] = mx;
    __syncthreads();
    if (tid == 0) {
        float m = smax[0];
#pragma unroll
        for (int i = 1; i < 8; i++) m = fmaxf(m, smax[i]);
        sbc[0] = m;
    }
    __syncthreads();
    mx = sbc[0];

    float e[8];
    e[0] = __expf(v0.x - mx); e[1] = __expf(v0.y - mx);
    e[2] = __expf(v0.z - mx); e[3] = __expf(v0.w - mx);
    e[4] = __expf(v1.x - mx); e[5] = __expf(v1.y - mx);
    e[6] = __expf(v1.z - mx); e[7] = __expf(v1.w - mx);
    float s = 0.f;
#pragma unroll
    for (int i = 0; i < 8; i++) s += e[i];
#pragma unroll
    for (int o = 16; o; o >>= 1) s += __shfl_xor_sync(0xffffffffu, s, o);
    if (lane == 0) ssum[wid] = s;
    __syncthreads();
    if (tid == 0) {
        float tt = 0.f;
#pragma unroll
        for (int i = 0; i < 8; i++) tt += ssum[i];
        sbc[1] = 1.f / tt;
    }
    __syncthreads();
    float inv = sbc[1];

    float4 o0 = make_float4(e[0] * inv, e[1] * inv, e[2] * inv, e[3] * inv);
    float4 o1 = make_float4(e[4] * inv, e[5] * inv, e[6] * inv, e[7] * inv);
    *(float4*)(p + tid * 8)     = o0;
    *(float4*)(p + tid * 8 + 4) = o1;
}

// ---------------------------------------------------------------------------
// PV (tensor core): ctx[q, h*64+d] = sum_k P[bh,q,k] * v[bh,k,d]
// Block 256(q) x 64(d), BK=32, 8 warps (4x2), warp tile 64x32.
// ---------------------------------------------------------------------------
__global__ __launch_bounds__(256) void pv_tc(
    const float* __restrict__ probs, const float* __restrict__ vg,
    float* __restrict__ ctx)
{
    __shared__ uint32_t Ps[256][36];   // [q][k]
    __shared__ uint32_t Vs[32][72];    // [k][d]

    const int tid  = threadIdx.x;
    const int w    = tid >> 5;
    const int lane = tid & 31;
    const int g    = lane >> 2;
    const int t    = lane & 3;
    const int wm   = (w & 3) * 64;
    const int wn   = (w >> 2) * 32;
    const int q0   = blockIdx.x * 256;
    const int bh   = blockIdx.y;
    const float* vbase = vg + (size_t)bh * S_ * D_;
    const size_t prow0 = (size_t)bh * S_ + q0;

    float acc[4][4][4];
#pragma unroll
    for (int mi = 0; mi < 4; mi++)
#pragma unroll
        for (int ni = 0; ni < 4; ni++)
#pragma unroll
            for (int r = 0; r < 4; r++) acc[mi][ni][r] = 0.f;

    for (int k0 = 0; k0 < S_; k0 += 32) {
#pragma unroll
        for (int i = 0; i < 8; i++) {
            int f = tid + 256 * i;      // 0..2047
            int r = f >> 3;             // 0..255
            int q = f & 7;              // 0..7
            float4 v = *(const float4*)(probs + (prow0 + r) * S_ + k0 + q * 4);
            uint4 u = make_uint4(f2t(v.x), f2t(v.y), f2t(v.z), f2t(v.w));
            *(uint4*)&Ps[r][q * 4] = u;
        }
#pragma unroll
        for (int i = 0; i < 2; i++) {
            int f = tid + 256 * i;      // 0..511
            int r = f >> 4;             // 0..31
            int q = f & 15;             // 0..15
            float4 v = *(const float4*)(vbase + (size_t)(k0 + r) * D_ + q * 4);
            uint4 u = make_uint4(f2t(v.x), f2t(v.y), f2t(v.z), f2t(v.w));
            *(uint4*)&Vs[r][q * 4] = u;
        }
        __syncthreads();

#pragma unroll
        for (int kk = 0; kk < 32; kk += 8) {
            uint32_t a[4][4], b[4][2];
#pragma unroll
            for (int mi = 0; mi < 4; mi++) {
                int mr = wm + 16 * mi + g;
                a[mi][0] = Ps[mr][kk + t];
                a[mi][1] = Ps[mr + 8][kk + t];
                a[mi][2] = Ps[mr][kk + t + 4];
                a[mi][3] = Ps[mr + 8][kk + t + 4];
            }
#pragma unroll
            for (int ni = 0; ni < 4; ni++) {
                b[ni][0] = Vs[kk + t][wn + 8 * ni + g];
                b[ni][1] = Vs[kk + t + 4][wn + 8 * ni + g];
            }
#pragma unroll
            for (int mi = 0; mi < 4; mi++)
#pragma unroll
                for (int ni = 0; ni < 4; ni++)
                    mma8(acc[mi][ni], a[mi][0], a[mi][1], a[mi][2], a[mi][3],
                         b[ni][0], b[ni][1]);
        }
        __syncthreads();
    }

    const int bb = bh / H_;
    const int h  = bh % H_;
#pragma unroll
    for (int mi = 0; mi < 4; mi++) {
        int r0 = q0 + wm + 16 * mi + g;
        int r1 = r0 + 8;
#pragma unroll
        for (int ni = 0; ni < 4; ni++) {
            int d = wn + 8 * ni + 2 * t;
            float2 v0 = make_float2(acc[mi][ni][0], acc[mi][ni][1]);
            float2 v1 = make_float2(acc[mi][ni][2], acc[mi][ni][3]);
            *(float2*)&ctx[((size_t)(bb * S_ + r0)) * HID_ + h * D_ + d] = v0;
            *(float2*)&ctx[((size_t)(bb * S_ + r1)) * HID_ + h * D_ + d] = v1;
        }
    }
}

// ---------------------------------------------------------------------------
extern "C" void kernel_launch(void* const* d_in, const int* in_sizes, int n_in,
                              void* d_out, int out_size)
{
    (void)in_sizes; (void)n_in; (void)out_size;
    const float* Q  = (const float*)d_in[0];
    const float* K  = (const float*)d_in[1];
    const float* V  = (const float*)d_in[2];
    const int*   mask = (const int*)d_in[3];
    const float* Wq = (const float*)d_in[4];
    const float* bq = (const float*)d_in[5];
    const float* Wk = (const float*)d_in[6];
    const float* bk = (const float*)d_in[7];
    const float* Wv = (const float*)d_in[8];
    const float* bv = (const float*)d_in[9];
    const float* Wo = (const float*)d_in[10];
    const float* bo = (const float*)d_in[11];

    float* out   = (float*)d_out;
    float* probs = out + OUTE;   // attn_prob region: [48, 2048, 2048]

    float* scratch = nullptr;
    cudaGetSymbolAddress((void**)&scratch, g_scratch);
    float* gq   = scratch;
    float* gk   = scratch + (size_t)OUTE;
    float* gv   = scratch + 2ull * OUTE;
    float* gctx = scratch + 3ull * OUTE;

    const int SCORES_SMEM = 2 * 128 * 68 * 4;   // 69632 bytes
    cudaFuncSetAttribute(scores_tc, cudaFuncAttributeMaxDynamicSharedMemorySize,
                         SCORES_SMEM);

    dim3 gproj(HID_ / 128, MROWS / 128);   // (6, 64)
    gemm_bias_tc<0><<<gproj, 256>>>(Q, Wq, bq, gq);
    gemm_bias_tc<0><<<gproj, 256>>>(K, Wk, bk, gk);
    gemm_bias_tc<0><<<gproj, 256>>>(V, Wv, bv, gv);

    scores_tc<<<dim3(S_ / 128, S_ / 128, BH_), 256, SCORES_SMEM>>>(gq, gk, mask, probs);
    softmax_kernel<<<dim3(BH_ * S_), 256>>>(probs);
    pv_tc<<<dim3(S_ / 256, BH_), 256>>>(probs, gv, gctx);

    gemm_bias_tc<1><<<gproj, 256>>>(gctx, Wo, bo, out);
}

// round 4
// speedup vs baseline: 2.5693x; 1.2591x over previous
#include <cuda_runtime.h>
#include <stdint.h>
#include <stddef.h>

#define B_ 4
#define S_ 2048
#define HID_ 768
#define H_ 12
#define D_ 64
#define BH_ 48
#define MROWS 8192
#define OUTE 6291456
#define SCALE_ 0.125f
#define FLTMAX_ 3.402823466e38f

// Scratch: q, k, v (BHSD each) + context (row-major [8192,768])
__device__ float g_scratch[4ull * 6291456ull];
// Bitmask: [B][S][S/32] = 4*2048*64 words
__device__ uint32_t g_bm[524288];

// ---------------------------------------------------------------------------
__device__ __forceinline__ uint32_t f2t(float f) {
    uint32_t r;
    asm("cvt.rna.tf32.f32 %0, %1;" : "=r"(r) : "f"(f));
    return r;
}

__device__ __forceinline__ void mma8(float* c,
    uint32_t a0, uint32_t a1, uint32_t a2, uint32_t a3,
    uint32_t b0, uint32_t b1)
{
    asm volatile(
        "mma.sync.aligned.m16n8k8.row.col.f32.tf32.tf32.f32 "
        "{%0,%1,%2,%3}, {%4,%5,%6,%7}, {%8,%9}, {%0,%1,%2,%3};"
        : "+f"(c[0]), "+f"(c[1]), "+f"(c[2]), "+f"(c[3])
        : "r"(a0), "r"(a1), "r"(a2), "r"(a3), "r"(b0), "r"(b1));
}

// ---------------------------------------------------------------------------
// Bitmask builder: mask int32 [4,2048,2048] -> bits (1 = masked)
// ---------------------------------------------------------------------------
__global__ __launch_bounds__(256) void build_bitmask(
    const int* __restrict__ mask, uint32_t* __restrict__ bm)
{
    int idx = blockIdx.x * 256 + threadIdx.x;      // word index < 524288
    const int* p = mask + (size_t)idx * 32;
    uint32_t r = 0;
#pragma unroll
    for (int j = 0; j < 8; j++) {
        int4 v = *(const int4*)(p + 4 * j);
        r |= (v.x != 0 ? 1u : 0u) << (4 * j);
        r |= (v.y != 0 ? 1u : 0u) << (4 * j + 1);
        r |= (v.z != 0 ? 1u : 0u) << (4 * j + 2);
        r |= (v.w != 0 ? 1u : 0u) << (4 * j + 3);
    }
    bm[idx] = r;
}

// ---------------------------------------------------------------------------
// QKV projection (tensor core), 3 GEMMs in one launch via blockIdx.z.
// C[8192,768] = X @ W + bias, scattered to BHSD.
// ---------------------------------------------------------------------------
__global__ __launch_bounds__(256, 2) void gemm_qkv(
    const float* __restrict__ Xq, const float* __restrict__ Xk, const float* __restrict__ Xv,
    const float* __restrict__ Wq, const float* __restrict__ Wk, const float* __restrict__ Wv,
    const float* __restrict__ bq, const float* __restrict__ bk, const float* __restrict__ bv,
    float* __restrict__ oq, float* __restrict__ ok, float* __restrict__ ov)
{
    const int z = blockIdx.z;
    const float* X    = (z == 0) ? Xq : (z == 1) ? Xk : Xv;
    const float* W    = (z == 0) ? Wq : (z == 1) ? Wk : Wv;
    const float* bias = (z == 0) ? bq : (z == 1) ? bk : bv;
    float* out        = (z == 0) ? oq : (z == 1) ? ok : ov;

    __shared__ uint32_t Xs[128][36];
    __shared__ uint32_t Ws[32][136];

    const int tid  = threadIdx.x;
    const int w    = tid >> 5;
    const int lane = tid & 31;
    const int g    = lane >> 2;
    const int t    = lane & 3;
    const int wm   = (w & 1) * 64;
    const int wn   = (w >> 1) * 32;
    const int m0   = blockIdx.y * 128;
    const int n0   = blockIdx.x * 128;

    float acc[4][4][4];
#pragma unroll
    for (int mi = 0; mi < 4; mi++)
#pragma unroll
        for (int ni = 0; ni < 4; ni++)
#pragma unroll
            for (int r = 0; r < 4; r++) acc[mi][ni][r] = 0.f;

    for (int k0 = 0; k0 < HID_; k0 += 32) {
#pragma unroll
        for (int i = 0; i < 4; i++) {
            int f = tid + 256 * i;
            int r = f >> 3, q = f & 7;
            float4 v = *(const float4*)(X + (size_t)(m0 + r) * HID_ + k0 + q * 4);
            *(uint4*)&Xs[r][q * 4] = make_uint4(f2t(v.x), f2t(v.y), f2t(v.z), f2t(v.w));
        }
#pragma unroll
        for (int i = 0; i < 4; i++) {
            int f = tid + 256 * i;
            int r = f >> 5, q = f & 31;
            float4 v = *(const float4*)(W + (size_t)(k0 + r) * HID_ + n0 + q * 4);
            *(uint4*)&Ws[r][q * 4] = make_uint4(f2t(v.x), f2t(v.y), f2t(v.z), f2t(v.w));
        }
        __syncthreads();
#pragma unroll
        for (int kk = 0; kk < 32; kk += 8) {
            uint32_t a[4][4], b[4][2];
#pragma unroll
            for (int mi = 0; mi < 4; mi++) {
                int mr = wm + 16 * mi + g;
                a[mi][0] = Xs[mr][kk + t];     a[mi][1] = Xs[mr + 8][kk + t];
                a[mi][2] = Xs[mr][kk + t + 4]; a[mi][3] = Xs[mr + 8][kk + t + 4];
            }
#pragma unroll
            for (int ni = 0; ni < 4; ni++) {
                b[ni][0] = Ws[kk + t][wn + 8 * ni + g];
                b[ni][1] = Ws[kk + t + 4][wn + 8 * ni + g];
            }
#pragma unroll
            for (int mi = 0; mi < 4; mi++)
#pragma unroll
                for (int ni = 0; ni < 4; ni++)
                    mma8(acc[mi][ni], a[mi][0], a[mi][1], a[mi][2], a[mi][3],
                         b[ni][0], b[ni][1]);
        }
        __syncthreads();
    }

#pragma unroll
    for (int mi = 0; mi < 4; mi++) {
        int r0 = m0 + wm + 16 * mi + g;
        int r1 = r0 + 8;
#pragma unroll
        for (int ni = 0; ni < 4; ni++) {
            int col = n0 + wn + 8 * ni + 2 * t;
            float bb0 = bias[col], bb1 = bias[col + 1];
            float2 v0 = make_float2(acc[mi][ni][0] + bb0, acc[mi][ni][1] + bb1);
            float2 v1 = make_float2(acc[mi][ni][2] + bb0, acc[mi][ni][3] + bb1);
            int h = col >> 6, d = col & 63;
            int b0r = r0 >> 11, s0 = r0 & 2047;
            int b1r = r1 >> 11, s1 = r1 & 2047;
            *(float2*)&out[(((size_t)(b0r * H_ + h) * S_ + s0) << 6) + d] = v0;
            *(float2*)&out[(((size_t)(b1r * H_ + h) * S_ + s1) << 6) + d] = v1;
        }
    }
}

// ---------------------------------------------------------------------------
// Out projection GEMM (row-major in/out)
// ---------------------------------------------------------------------------
__global__ __launch_bounds__(256, 2) void gemm_out(
    const float* __restrict__ X, const float* __restrict__ W,
    const float* __restrict__ bias, float* __restrict__ out)
{
    __shared__ uint32_t Xs[128][36];
    __shared__ uint32_t Ws[32][136];
    const int tid  = threadIdx.x;
    const int w    = tid >> 5;
    const int lane = tid & 31;
    const int g    = lane >> 2;
    const int t    = lane & 3;
    const int wm   = (w & 1) * 64;
    const int wn   = (w >> 1) * 32;
    const int m0   = blockIdx.y * 128;
    const int n0   = blockIdx.x * 128;

    float acc[4][4][4];
#pragma unroll
    for (int mi = 0; mi < 4; mi++)
#pragma unroll
        for (int ni = 0; ni < 4; ni++)
#pragma unroll
            for (int r = 0; r < 4; r++) acc[mi][ni][r] = 0.f;

    for (int k0 = 0; k0 < HID_; k0 += 32) {
#pragma unroll
        for (int i = 0; i < 4; i++) {
            int f = tid + 256 * i;
            int r = f >> 3, q = f & 7;
            float4 v = *(const float4*)(X + (size_t)(m0 + r) * HID_ + k0 + q * 4);
            *(uint4*)&Xs[r][q * 4] = make_uint4(f2t(v.x), f2t(v.y), f2t(v.z), f2t(v.w));
        }
#pragma unroll
        for (int i = 0; i < 4; i++) {
            int f = tid + 256 * i;
            int r = f >> 5, q = f & 31;
            float4 v = *(const float4*)(W + (size_t)(k0 + r) * HID_ + n0 + q * 4);
            *(uint4*)&Ws[r][q * 4] = make_uint4(f2t(v.x), f2t(v.y), f2t(v.z), f2t(v.w));
        }
        __syncthreads();
#pragma unroll
        for (int kk = 0; kk < 32; kk += 8) {
            uint32_t a[4][4], b[4][2];
#pragma unroll
            for (int mi = 0; mi < 4; mi++) {
                int mr = wm + 16 * mi + g;
                a[mi][0] = Xs[mr][kk + t];     a[mi][1] = Xs[mr + 8][kk + t];
                a[mi][2] = Xs[mr][kk + t + 4]; a[mi][3] = Xs[mr + 8][kk + t + 4];
            }
#pragma unroll
            for (int ni = 0; ni < 4; ni++) {
                b[ni][0] = Ws[kk + t][wn + 8 * ni + g];
                b[ni][1] = Ws[kk + t + 4][wn + 8 * ni + g];
            }
#pragma unroll
            for (int mi = 0; mi < 4; mi++)
#pragma unroll
                for (int ni = 0; ni < 4; ni++)
                    mma8(acc[mi][ni], a[mi][0], a[mi][1], a[mi][2], a[mi][3],
                         b[ni][0], b[ni][1]);
        }
        __syncthreads();
    }

#pragma unroll
    for (int mi = 0; mi < 4; mi++) {
        int r0 = m0 + wm + 16 * mi + g;
        int r1 = r0 + 8;
#pragma unroll
        for (int ni = 0; ni < 4; ni++) {
            int col = n0 + wn + 8 * ni + 2 * t;
            float bb0 = bias[col], bb1 = bias[col + 1];
            *(float2*)&out[(size_t)r0 * HID_ + col] =
                make_float2(acc[mi][ni][0] + bb0, acc[mi][ni][1] + bb1);
            *(float2*)&out[(size_t)r1 * HID_ + col] =
                make_float2(acc[mi][ni][2] + bb0, acc[mi][ni][3] + bb1);
        }
    }
}

// ---------------------------------------------------------------------------
// Fused attention: per block (bh, 128 q rows).
// Pass 1: online softmax stats (m, S) over all k with masked tf32 scores.
// Pass 2: recompute scores, p = exp(s-m)/S, write probs, PV on tensor cores.
// 8 warps; warp tile = 16 q rows x full 64-wide k tile.
// Smem (dynamic): Qs[128][68] Ks[64][68] Vs[64][72] Ps[128][72] = 105KB.
// ---------------------------------------------------------------------------
#define QS_PITCH 68
#define KS_PITCH 68
#define VS_PITCH 72
#define PS_PITCH 72
#define QS_OFF 0
#define KS_OFF (128 * QS_PITCH)
#define VS_OFF (KS_OFF + 64 * KS_PITCH)
#define PS_OFF (VS_OFF + 64 * VS_PITCH)
#define FUSED_SMEM ((PS_OFF + 128 * PS_PITCH) * 4)

__global__ __launch_bounds__(256, 2) void fused_attn(
    const float* __restrict__ qg, const float* __restrict__ kg,
    const float* __restrict__ vg, const uint32_t* __restrict__ bm,
    float* __restrict__ probs, float* __restrict__ ctx)
{
    extern __shared__ uint32_t sh[];
    uint32_t* Qs = sh + QS_OFF;
    uint32_t* Ks = sh + KS_OFF;
    uint32_t* Vs = sh + VS_OFF;
    uint32_t* Ps = sh + PS_OFF;

    const int tid  = threadIdx.x;
    const int w    = tid >> 5;
    const int lane = tid & 31;
    const int g    = lane >> 2;
    const int t    = lane & 3;
    const int wr   = w * 16;
    const int q0   = blockIdx.x * 128;
    const int bh   = blockIdx.y;
    const int bb   = bh / H_;
    const int h    = bh % H_;
    const float* qbase = qg + (size_t)bh * S_ * D_;
    const float* kbase = kg + (size_t)bh * S_ * D_;
    const float* vbase = vg + (size_t)bh * S_ * D_;

    const int r0 = q0 + wr + g;      // this thread's two q rows
    const int r1 = r0 + 8;
    const uint32_t* bm0 = bm + ((size_t)bb * S_ + r0) * 64;
    const uint32_t* bm1 = bm + ((size_t)bb * S_ + r1) * 64;

    // Load Q tile once: 128x64
#pragma unroll
    for (int i = 0; i < 8; i++) {
        int f = tid + 256 * i;
        int r = f >> 4, q = f & 15;
        float4 v = *(const float4*)(qbase + (size_t)(q0 + r) * D_ + q * 4);
        uint4 u = make_uint4(f2t(v.x), f2t(v.y), f2t(v.z), f2t(v.w));
        *(uint4*)&Qs[r * QS_PITCH + q * 4] = u;
    }
    __syncthreads();

    float m0v = -FLTMAX_, m1v = -FLTMAX_;
    float s0v = 0.f, s1v = 0.f;

    // ---------------- Pass 1: stats ----------------
    for (int k0 = 0; k0 < S_; k0 += 64) {
#pragma unroll
        for (int i = 0; i < 4; i++) {
            int f = tid + 256 * i;
            int r = f >> 4, q = f & 15;
            float4 v = *(const float4*)(kbase + (size_t)(k0 + r) * D_ + q * 4);
            uint4 u = make_uint4(f2t(v.x), f2t(v.y), f2t(v.z), f2t(v.w));
            *(uint4*)&Ks[r * KS_PITCH + q * 4] = u;
        }
        __syncthreads();

        float acc[8][4];
#pragma unroll
        for (int ni = 0; ni < 8; ni++)
#pragma unroll
            for (int r = 0; r < 4; r++) acc[ni][r] = 0.f;

#pragma unroll
        for (int kk = 0; kk < 64; kk += 8) {
            uint32_t a0 = Qs[(wr + g) * QS_PITCH + kk + t];
            uint32_t a1 = Qs[(wr + g + 8) * QS_PITCH + kk + t];
            uint32_t a2 = Qs[(wr + g) * QS_PITCH + kk + t + 4];
            uint32_t a3 = Qs[(wr + g + 8) * QS_PITCH + kk + t + 4];
#pragma unroll
            for (int ni = 0; ni < 8; ni++) {
                uint32_t b0 = Ks[(8 * ni + g) * KS_PITCH + kk + t];
                uint32_t b1 = Ks[(8 * ni + g) * KS_PITCH + kk + t + 4];
                mma8(acc[ni], a0, a1, a2, a3, b0, b1);
            }
        }

        uint2 w0 = *(const uint2*)(bm0 + (k0 >> 5));
        uint2 w1 = *(const uint2*)(bm1 + (k0 >> 5));
        float lm0 = -FLTMAX_, lm1 = -FLTMAX_;
#pragma unroll
        for (int ni = 0; ni < 8; ni++) {
            uint32_t sel0 = (ni < 4) ? w0.x : w0.y;
            uint32_t sel1 = (ni < 4) ? w1.x : w1.y;
            int bit = (8 * ni + 2 * t) & 31;
            acc[ni][0] = ((sel0 >> bit) & 1)       ? -1e9f : acc[ni][0] * SCALE_;
            acc[ni][1] = ((sel0 >> (bit + 1)) & 1) ? -1e9f : acc[ni][1] * SCALE_;
            acc[ni][2] = ((sel1 >> bit) & 1)       ? -1e9f : acc[ni][2] * SCALE_;
            acc[ni][3] = ((sel1 >> (bit + 1)) & 1) ? -1e9f : acc[ni][3] * SCALE_;
            lm0 = fmaxf(lm0, fmaxf(acc[ni][0], acc[ni][1]));
            lm1 = fmaxf(lm1, fmaxf(acc[ni][2], acc[ni][3]));
        }
        lm0 = fmaxf(lm0, __shfl_xor_sync(0xffffffffu, lm0, 1));
        lm0 = fmaxf(lm0, __shfl_xor_sync(0xffffffffu, lm0, 2));
        lm1 = fmaxf(lm1, __shfl_xor_sync(0xffffffffu, lm1, 1));
        lm1 = fmaxf(lm1, __shfl_xor_sync(0xffffffffu, lm1, 2));

        float mn0 = fmaxf(m0v, lm0);
        float mn1 = fmaxf(m1v, lm1);
        float sc0 = __expf(m0v - mn0);
        float sc1 = __expf(m1v - mn1);
        float ls0 = 0.f, ls1 = 0.f;
#pragma unroll
        for (int ni = 0; ni < 8; ni++) {
            ls0 += __expf(acc[ni][0] - mn0) + __expf(acc[ni][1] - mn0);
            ls1 += __expf(acc[ni][2] - mn1) + __expf(acc[ni][3] - mn1);
        }
        s0v = s0v * sc0 + ls0;
        s1v = s1v * sc1 + ls1;
        m0v = mn0; m1v = mn1;
        __syncthreads();
    }

    // Finalize: quad-sum S, inverse
    float S0 = s0v + __shfl_xor_sync(0xffffffffu, s0v, 1);
    S0 += __shfl_xor_sync(0xffffffffu, S0, 2);
    float S1 = s1v + __shfl_xor_sync(0xffffffffu, s1v, 1);
    S1 += __shfl_xor_sync(0xffffffffu, S1, 2);
    float inv0 = 1.f / S0;
    float inv1 = 1.f / S1;

    float accv[8][4];
#pragma unroll
    for (int ni = 0; ni < 8; ni++)
#pragma unroll
        for (int r = 0; r < 4; r++) accv[ni][r] = 0.f;

    float* pr0 = probs + ((size_t)bh * S_ + r0) * S_;
    float* pr1 = probs + ((size_t)bh * S_ + r1) * S_;

    // ---------------- Pass 2: probs + PV ----------------
    for (int k0 = 0; k0 < S_; k0 += 64) {
#pragma unroll
        for (int i = 0; i < 4; i++) {
            int f = tid + 256 * i;
            int r = f >> 4, q = f & 15;
            float4 v = *(const float4*)(kbase + (size_t)(k0 + r) * D_ + q * 4);
            *(uint4*)&Ks[r * KS_PITCH + q * 4] =
                make_uint4(f2t(v.x), f2t(v.y), f2t(v.z), f2t(v.w));
        }
#pragma unroll
        for (int i = 0; i < 4; i++) {
            int f = tid + 256 * i;
            int r = f >> 4, q = f & 15;
            float4 v = *(const float4*)(vbase + (size_t)(k0 + r) * D_ + q * 4);
            *(uint4*)&Vs[r * VS_PITCH + q * 4] =
                make_uint4(f2t(v.x), f2t(v.y), f2t(v.z), f2t(v.w));
        }
        __syncthreads();

        float acc[8][4];
#pragma unroll
        for (int ni = 0; ni < 8; ni++)
#pragma unroll
            for (int r = 0; r < 4; r++) acc[ni][r] = 0.f;

#pragma unroll
        for (int kk = 0; kk < 64; kk += 8) {
            uint32_t a0 = Qs[(wr + g) * QS_PITCH + kk + t];
            uint32_t a1 = Qs[(wr + g + 8) * QS_PITCH + kk + t];
            uint32_t a2 = Qs[(wr + g) * QS_PITCH + kk + t + 4];
            uint32_t a3 = Qs[(wr + g + 8) * QS_PITCH + kk + t + 4];
#pragma unroll
            for (int ni = 0; ni < 8; ni++) {
                uint32_t b0 = Ks[(8 * ni + g) * KS_PITCH + kk + t];
                uint32_t b1 = Ks[(8 * ni + g) * KS_PITCH + kk + t + 4];
                mma8(acc[ni], a0, a1, a2, a3, b0, b1);
            }
        }

        uint2 w0 = *(const uint2*)(bm0 + (k0 >> 5));
        uint2 w1 = *(const uint2*)(bm1 + (k0 >> 5));
#pragma unroll
        for (int ni = 0; ni < 8; ni++) {
            uint32_t sel0 = (ni < 4) ? w0.x : w0.y;
            uint32_t sel1 = (ni < 4) ? w1.x : w1.y;
            int bit = (8 * ni + 2 * t) & 31;
            float v00 = ((sel0 >> bit) & 1)       ? -1e9f : acc[ni][0] * SCALE_;
            float v01 = ((sel0 >> (bit + 1)) & 1) ? -1e9f : acc[ni][1] * SCALE_;
            float v10 = ((sel1 >> bit) & 1)       ? -1e9f : acc[ni][2] * SCALE_;
            float v11 = ((sel1 >> (bit + 1)) & 1) ? -1e9f : acc[ni][3] * SCALE_;
            float p00 = __expf(v00 - m0v) * inv0;
            float p01 = __expf(v01 - m0v) * inv0;
            float p10 = __expf(v10 - m1v) * inv1;
            float p11 = __expf(v11 - m1v) * inv1;
            int c = k0 + 8 * ni + 2 * t;
            *(float2*)(pr0 + c) = make_float2(p00, p01);
            *(float2*)(pr1 + c) = make_float2(p10, p11);
            int cl = 8 * ni + 2 * t;
            *(uint2*)&Ps[(wr + g) * PS_PITCH + cl]     = make_uint2(f2t(p00), f2t(p01));
            *(uint2*)&Ps[(wr + g + 8) * PS_PITCH + cl] = make_uint2(f2t(p10), f2t(p11));
        }
        __syncwarp();

#pragma unroll
        for (int kk = 0; kk < 64; kk += 8) {
            uint32_t a0 = Ps[(wr + g) * PS_PITCH + kk + t];
            uint32_t a1 = Ps[(wr + g + 8) * PS_PITCH + kk + t];
            uint32_t a2 = Ps[(wr + g) * PS_PITCH + kk + t + 4];
            uint32_t a3 = Ps[(wr + g + 8) * PS_PITCH + kk + t + 4];
#pragma unroll
            for (int ni = 0; ni < 8; ni++) {
                uint32_t b0 = Vs[(kk + t) * VS_PITCH + 8 * ni + g];
                uint32_t b1 = Vs[(kk + t + 4) * VS_PITCH + 8 * ni + g];
                mma8(accv[ni], a0, a1, a2, a3, b0, b1);
            }
        }
        __syncthreads();
    }

    // Epilogue: context rows r0, r1 -> [bb*S + row][h*64 + col]
#pragma unroll
    for (int ni = 0; ni < 8; ni++) {
        int col = h * D_ + 8 * ni + 2 * t;
        *(float2*)&ctx[((size_t)(bb * S_ + r0)) * HID_ + col] =
            make_float2(accv[ni][0], accv[ni][1]);
        *(float2*)&ctx[((size_t)(bb * S_ + r1)) * HID_ + col] =
            make_float2(accv[ni][2], accv[ni][3]);
    }
}

// ---------------------------------------------------------------------------
extern "C" void kernel_launch(void* const* d_in, const int* in_sizes, int n_in,
                              void* d_out, int out_size)
{
    (void)in_sizes; (void)n_in; (void)out_size;
    const float* Q  = (const float*)d_in[0];
    const float* K  = (const float*)d_in[1];
    const float* V  = (const float*)d_in[2];
    const int*   mask = (const int*)d_in[3];
    const float* Wq = (const float*)d_in[4];
    const float* bq = (const float*)d_in[5];
    const float* Wk = (const float*)d_in[6];
    const float* bk = (const float*)d_in[7];
    const float* Wv = (const float*)d_in[8];
    const float* bv = (const float*)d_in[9];
    const float* Wo = (const float*)d_in[10];
    const float* bo = (const float*)d_in[11];

    float* out   = (float*)d_out;
    float* probs = out + OUTE;

    float* scratch = nullptr;
    cudaGetSymbolAddress((void**)&scratch, g_scratch);
    uint32_t* bmp = nullptr;
    cudaGetSymbolAddress((void**)&bmp, g_bm);
    float* gq   = scratch;
    float* gk   = scratch + (size_t)OUTE;
    float* gv   = scratch + 2ull * OUTE;
    float* gctx = scratch + 3ull * OUTE;

    static int attr_set = 0;
    if (!attr_set) {
        cudaFuncSetAttribute(fused_attn, cudaFuncAttributeMaxDynamicSharedMemorySize,
                             FUSED_SMEM);
        attr_set = 1;
    }

    build_bitmask<<<2048, 256>>>(mask, bmp);
    gemm_qkv<<<dim3(HID_ / 128, MROWS / 128, 3), 256>>>(
        Q, K, V, Wq, Wk, Wv, bq, bk, bv, gq, gk, gv);
    fused_attn<<<dim3(S_ / 128, BH_), 256, FUSED_SMEM>>>(gq, gk, gv, bmp, probs, gctx);
    gemm_out<<<dim3(HID_ / 128, MROWS / 128), 256>>>(gctx, Wo, bo, out);
}